// round 2
// baseline (speedup 1.0000x reference)
#include <cuda_runtime.h>
#include <cstddef>

// Shapes (fixed by the problem)
//  x_f:    (128, 256, 31, 31) f32
//  z_f:    (128, 256, 7, 7)   f32
//  heat_w: (1, 256, 3, 3), heat_b: (1,)
//  reg_w:  (4, 256, 3, 3), reg_b:  (4,)
//  out = concat(pred_heat (128,1,23,23), pred_reg (128,4,23,23)) f32

#define NB 128
#define NC 256

// Scratch: corr (128, 256, 25, 25) f32 = 81.92 MB (static __device__, allowed)
__device__ float g_corr[(size_t)NB * NC * 625];

// ---------------------------------------------------------------------------
// K1: depthwise cross-correlation.
// Grid: 128*32 CTAs; CTA = (n, block of 8 channels). 256 threads.
// Thread tile: 5x5 corr outputs of one channel (threads 0..199 compute).
// z (49 taps) held in registers; x row segments (11 floats) register-cached,
// so smem traffic is ~0.4 B per FMA (crossbar limit is 1 B/FMA at full rate).
// ---------------------------------------------------------------------------
__global__ __launch_bounds__(256, 2)
void xcorr_kernel(const float* __restrict__ x_f, const float* __restrict__ z_f)
{
    extern __shared__ float sm[];
    float* sx = sm;                    // 8 * 31 * 33 (row stride 33: pad breaks banks)
    float* sz = sx + 8 * 31 * 33;      // 8 * 49
    float* sc = sz + 8 * 49;           // 8 * 625 (corr staging, coalesced store)

    const int b   = blockIdx.x;
    const int n   = b >> 5;            // 32 channel-blocks per n
    const int c0  = (b & 31) * 8;
    const int tid = threadIdx.x;

    // Stage x: 8 channels x 961 floats, coalesced read, padded write.
    const float* xg = x_f + ((size_t)n * NC + c0) * 961;
    for (int i = tid; i < 8 * 961; i += 256) {
        int ch = i / 961;
        int p  = i - ch * 961;
        int r  = p / 31;
        int cc = p - r * 31;
        sx[ch * (31 * 33) + r * 33 + cc] = xg[i];
    }
    // Stage z: 8 x 49.
    const float* zg = z_f + ((size_t)n * NC + c0) * 49;
    for (int i = tid; i < 8 * 49; i += 256) sz[i] = zg[i];
    __syncthreads();

    if (tid < 200) {
        const int ch = tid / 25;
        const int t  = tid - ch * 25;
        const int ty = t / 5, tx = t - (t / 5) * 5;
        const int row0 = ty * 5, col0 = tx * 5;

        float zr[49];
        #pragma unroll
        for (int i = 0; i < 49; i++) zr[i] = sz[ch * 49 + i];

        float acc[25];
        #pragma unroll
        for (int i = 0; i < 25; i++) acc[i] = 0.0f;

        const float* sxc = sx + ch * (31 * 33) + row0 * 33 + col0;

        // Sweep the 11 x-rows this 5x5 tile touches; each row feeds up to
        // 5 output rows x 7 taps x 5 cols of FMAs from an 11-float reg cache.
        #pragma unroll
        for (int r = 0; r < 11; r++) {
            float xr[11];
            #pragma unroll
            for (int k = 0; k < 11; k++) xr[k] = sxc[r * 33 + k];
            #pragma unroll
            for (int dy = 0; dy < 5; dy++) {
                if (dy < r - 6 || dy > r) continue;   // static after unroll
                const int u = r - dy;
                #pragma unroll
                for (int v = 0; v < 7; v++) {
                    const float zv = zr[u * 7 + v];
                    #pragma unroll
                    for (int j = 0; j < 5; j++)
                        acc[dy * 5 + j] += zv * xr[v + j];
                }
            }
        }

        #pragma unroll
        for (int dy = 0; dy < 5; dy++)
            #pragma unroll
            for (int j = 0; j < 5; j++)
                sc[ch * 625 + (row0 + dy) * 25 + col0 + j] = acc[dy * 5 + j];
    }
    __syncthreads();

    // Coalesced corr store.
    float* cg = g_corr + ((size_t)n * NC + c0) * 625;
    for (int i = tid; i < 8 * 625; i += 256) cg[i] = sc[i];
}

// ---------------------------------------------------------------------------
// K2: two fused 3x3 VALID convs (heat: 1ch, reg: 4ch) over corr + bias.
// Grid: 128 CTAs (one per n), 288 threads.
// Thread owns a 1x2 spatial pair for ALL 5 output channels: the 3x4 corr
// window is loaded once and reused 5x; weights are warp-uniform broadcasts.
// Channels processed in chunks of 8 staged in smem (stride-26 rows).
// ---------------------------------------------------------------------------
__global__ __launch_bounds__(288, 2)
void head_kernel(const float* __restrict__ heat_w, const float* __restrict__ heat_b,
                 const float* __restrict__ reg_w,  const float* __restrict__ reg_b,
                 float* __restrict__ out)
{
    __shared__ float scr[8 * 650];   // 8 channels x 25 rows x stride 26
    __shared__ float sw[5 * 8 * 9];  // [o][ch][tap]

    const int n   = blockIdx.x;
    const int tid = threadIdx.x;

    const int  tile  = tid;               // 23 rows x 12 col-pairs = 276 tiles
    const bool valid = tile < 276;
    const int  y  = tile / 12;
    const int  x0 = (tile - y * 12) * 2;  // x0 in {0..22}; x0+1==23 is discarded

    float acc[2][5];
    #pragma unroll
    for (int j = 0; j < 2; j++)
        #pragma unroll
        for (int o = 0; o < 5; o++) acc[j][o] = 0.0f;

    for (int c0 = 0; c0 < NC; c0 += 8) {
        const float* cg = g_corr + ((size_t)n * NC + c0) * 625;
        for (int i = tid; i < 8 * 625; i += 288) {
            int ch = i / 625;
            int p  = i - ch * 625;
            int r  = p / 25;
            int cc = p - r * 25;
            scr[ch * 650 + r * 26 + cc] = cg[i];
        }
        if (tid < 8 * 25) {                         // zero the pad column
            int ch = tid / 25, r = tid - ch * 25;
            scr[ch * 650 + r * 26 + 25] = 0.0f;
        }
        for (int i = tid; i < 360; i += 288) {      // weights [o][ch][tap]
            int o = i / 72, rem = i - o * 72;
            int ch = rem / 9, tap = rem - ch * 9;
            sw[i] = (o == 0) ? heat_w[(c0 + ch) * 9 + tap]
                             : reg_w[(((o - 1) * NC) + c0 + ch) * 9 + tap];
        }
        __syncthreads();

        if (valid) {
            for (int ch = 0; ch < 8; ch++) {
                float cw[3][4];
                #pragma unroll
                for (int dy = 0; dy < 3; dy++)
                    #pragma unroll
                    for (int dx = 0; dx < 4; dx++)
                        cw[dy][dx] = scr[ch * 650 + (y + dy) * 26 + x0 + dx];
                #pragma unroll
                for (int o = 0; o < 5; o++) {
                    #pragma unroll
                    for (int dy = 0; dy < 3; dy++)
                        #pragma unroll
                        for (int dx = 0; dx < 3; dx++) {
                            const float w = sw[(o * 8 + ch) * 9 + dy * 3 + dx];
                            acc[0][o] += w * cw[dy][dx];
                            acc[1][o] += w * cw[dy][dx + 1];
                        }
                }
            }
        }
        __syncthreads();
    }

    if (valid) {
        const float hb = heat_b[0];
        #pragma unroll
        for (int j = 0; j < 2; j++) {
            const int x = x0 + j;
            if (x >= 23) continue;
            const int sp = y * 23 + x;
            out[(size_t)n * 529 + sp] = acc[j][0] + hb;
            #pragma unroll
            for (int o = 0; o < 4; o++)
                out[(size_t)NB * 529 + ((size_t)n * 4 + o) * 529 + sp] =
                    acc[j][1 + o] + reg_b[o];
        }
    }
}

// ---------------------------------------------------------------------------
extern "C" void kernel_launch(void* const* d_in, const int* in_sizes, int n_in,
                              void* d_out, int out_size)
{
    // Robust input binding by element count (all counts are distinct).
    const float *x_f = nullptr, *z_f = nullptr, *heat_w = nullptr,
                *heat_b = nullptr, *reg_w = nullptr, *reg_b = nullptr;
    for (int i = 0; i < n_in; i++) {
        switch (in_sizes[i]) {
            case 128 * 256 * 31 * 31: x_f    = (const float*)d_in[i]; break;
            case 128 * 256 * 7 * 7:   z_f    = (const float*)d_in[i]; break;
            case 1 * 256 * 3 * 3:     heat_w = (const float*)d_in[i]; break;
            case 1:                   heat_b = (const float*)d_in[i]; break;
            case 4 * 256 * 3 * 3:     reg_w  = (const float*)d_in[i]; break;
            case 4:                   reg_b  = (const float*)d_in[i]; break;
            default: break;
        }
    }
    float* out = (float*)d_out;

    const int smem1 = (8 * 31 * 33 + 8 * 49 + 8 * 625) * (int)sizeof(float); // ~54 KB
    static bool attr_set = false;  // attribute is idempotent & deterministic
    (void)attr_set;
    cudaFuncSetAttribute(xcorr_kernel,
                         cudaFuncAttributeMaxDynamicSharedMemorySize, smem1);

    xcorr_kernel<<<NB * 32, 256, smem1>>>(x_f, z_f);
    head_kernel<<<NB, 288>>>(heat_w, heat_b, reg_w, reg_b, out);
}

// round 3
// speedup vs baseline: 1.9160x; 1.9160x over previous
#include <cuda_runtime.h>
#include <cstddef>

// Shapes (fixed by the problem)
//  x_f:    (128, 256, 31, 31) f32
//  z_f:    (128, 256, 7, 7)   f32
//  heat_w: (1, 256, 3, 3), heat_b: (1,)
//  reg_w:  (4, 256, 3, 3), reg_b:  (4,)
//  out = concat(pred_heat (128,1,23,23), pred_reg (128,4,23,23)) f32

#define NB 128
#define NC 256
#define HEAT_ELEMS (NB * 529)          // 67712
#define OUT_ELEMS  (NB * 5 * 529)      // 338560

// ---------------------------------------------------------------------------
// K0: write biases into out (out is poisoned to 0xAA by the harness).
// The fused kernel then accumulates partial conv sums on top via atomicAdd.
// ---------------------------------------------------------------------------
__global__ void init_out_kernel(const float* __restrict__ heat_b,
                                const float* __restrict__ reg_b,
                                float* __restrict__ out)
{
    int i = blockIdx.x * 256 + threadIdx.x;
    if (i >= OUT_ELEMS) return;
    if (i < HEAT_ELEMS) {
        out[i] = heat_b[0];
    } else {
        int j = i - HEAT_ELEMS;
        int o = (j / 529) & 3;         // (j/529) % 4
        out[i] = reg_b[o];
    }
}

// ---------------------------------------------------------------------------
// K1 (fused): depthwise xcorr + both 3x3 head convs.
// Grid: 128*32 CTAs; CTA = (n, block of 8 channels). 256 threads.
//
// Phase A: stage x (padded rows), z, head weights into smem.
// Phase B: threads 0..199 each compute a 5x5 corr tile of one channel
//          fully in registers (z taps register-resident), write to smem.
// Phase C: all 256 threads compute the 8-channel partial 3x3 conv for all
//          5 output channels over the 23x23 grid and atomicAdd (REDG) the
//          partial sums into out. Cross-channel-block reduction happens in
//          L2's atomic units; collision degree per address is 32.
// ---------------------------------------------------------------------------
__global__ __launch_bounds__(256, 2)
void fused_kernel(const float* __restrict__ x_f, const float* __restrict__ z_f,
                  const float* __restrict__ heat_w, const float* __restrict__ reg_w,
                  float* __restrict__ out)
{
    extern __shared__ float sm[];
    float* sx = sm;                    // 8 * 31 * 33  (row stride 33)
    float* sz = sx + 8 * 31 * 33;      // 8 * 49
    float* sc = sz + 8 * 49;           // 8 * 25 * 26  (corr, row stride 26)
    float* sw = sc + 8 * 650;          // 5 * 8 * 9    ([o][ch][tap])

    const int b   = blockIdx.x;
    const int n   = b >> 5;            // 32 channel-blocks per n
    const int c0  = (b & 31) * 8;
    const int tid = threadIdx.x;

    // --- Phase A: staging ---
    const float* xg = x_f + ((size_t)n * NC + c0) * 961;
    for (int i = tid; i < 8 * 961; i += 256) {
        int ch = i / 961;
        int p  = i - ch * 961;
        int r  = p / 31;
        int cc = p - r * 31;
        sx[ch * (31 * 33) + r * 33 + cc] = xg[i];
    }
    const float* zg = z_f + ((size_t)n * NC + c0) * 49;
    for (int i = tid; i < 8 * 49; i += 256) sz[i] = zg[i];
    for (int i = tid; i < 360; i += 256) {          // weights [o][ch][tap]
        int o = i / 72, rem = i - o * 72;
        int ch = rem / 9, tap = rem - ch * 9;
        sw[i] = (o == 0) ? heat_w[(c0 + ch) * 9 + tap]
                         : reg_w[(((o - 1) * NC) + c0 + ch) * 9 + tap];
    }
    __syncthreads();

    // --- Phase B: depthwise xcorr, 5x5 register tile per thread ---
    if (tid < 200) {
        const int ch = tid / 25;
        const int t  = tid - ch * 25;
        const int ty = t / 5, tx = t - (t / 5) * 5;
        const int row0 = ty * 5, col0 = tx * 5;

        float zr[49];
        #pragma unroll
        for (int i = 0; i < 49; i++) zr[i] = sz[ch * 49 + i];

        float acc[25];
        #pragma unroll
        for (int i = 0; i < 25; i++) acc[i] = 0.0f;

        const float* sxc = sx + ch * (31 * 33) + row0 * 33 + col0;

        #pragma unroll
        for (int r = 0; r < 11; r++) {
            float xr[11];
            #pragma unroll
            for (int k = 0; k < 11; k++) xr[k] = sxc[r * 33 + k];
            #pragma unroll
            for (int dy = 0; dy < 5; dy++) {
                if (dy < r - 6 || dy > r) continue;   // static after unroll
                const int u = r - dy;
                #pragma unroll
                for (int v = 0; v < 7; v++) {
                    const float zv = zr[u * 7 + v];
                    #pragma unroll
                    for (int j = 0; j < 5; j++)
                        acc[dy * 5 + j] += zv * xr[v + j];
                }
            }
        }

        #pragma unroll
        for (int dy = 0; dy < 5; dy++)
            #pragma unroll
            for (int j = 0; j < 5; j++)
                sc[ch * 650 + (row0 + dy) * 26 + col0 + j] = acc[dy * 5 + j];
    }
    __syncthreads();

    // --- Phase C: partial 3x3 convs (5 out channels) + REDG accumulate ---
    for (int i = tid; i < 529; i += 256) {
        const int y = i / 23;
        const int x = i - y * 23;

        float a[5];
        #pragma unroll
        for (int o = 0; o < 5; o++) a[o] = 0.0f;

        #pragma unroll 2
        for (int ch = 0; ch < 8; ch++) {
            float cw[3][3];
            #pragma unroll
            for (int dy = 0; dy < 3; dy++)
                #pragma unroll
                for (int dx = 0; dx < 3; dx++)
                    cw[dy][dx] = sc[ch * 650 + (y + dy) * 26 + x + dx];
            #pragma unroll
            for (int o = 0; o < 5; o++) {
                const float* w = &sw[(o * 8 + ch) * 9];
                #pragma unroll
                for (int dy = 0; dy < 3; dy++)
                    #pragma unroll
                    for (int dx = 0; dx < 3; dx++)
                        a[o] += w[dy * 3 + dx] * cw[dy][dx];
            }
        }

        atomicAdd(&out[(size_t)n * 529 + i], a[0]);      // heat
        #pragma unroll
        for (int o = 0; o < 4; o++)
            atomicAdd(&out[HEAT_ELEMS + ((size_t)n * 4 + o) * 529 + i], a[1 + o]);
    }
}

// ---------------------------------------------------------------------------
extern "C" void kernel_launch(void* const* d_in, const int* in_sizes, int n_in,
                              void* d_out, int out_size)
{
    // Robust input binding by element count (all counts are distinct).
    const float *x_f = nullptr, *z_f = nullptr, *heat_w = nullptr,
                *heat_b = nullptr, *reg_w = nullptr, *reg_b = nullptr;
    for (int i = 0; i < n_in; i++) {
        switch (in_sizes[i]) {
            case 128 * 256 * 31 * 31: x_f    = (const float*)d_in[i]; break;
            case 128 * 256 * 7 * 7:   z_f    = (const float*)d_in[i]; break;
            case 1 * 256 * 3 * 3:     heat_w = (const float*)d_in[i]; break;
            case 1:                   heat_b = (const float*)d_in[i]; break;
            case 4 * 256 * 3 * 3:     reg_w  = (const float*)d_in[i]; break;
            case 4:                   reg_b  = (const float*)d_in[i]; break;
            default: break;
        }
    }
    float* out = (float*)d_out;

    const int smem1 = (8 * 31 * 33 + 8 * 49 + 8 * 650 + 360) * (int)sizeof(float); // ~56.5 KB
    cudaFuncSetAttribute(fused_kernel,
                         cudaFuncAttributeMaxDynamicSharedMemorySize, smem1);

    init_out_kernel<<<(OUT_ELEMS + 255) / 256, 256>>>(heat_b, reg_b, out);
    fused_kernel<<<NB * 32, 256, smem1>>>(x_f, z_f, heat_w, reg_w, out);
}

// round 4
// speedup vs baseline: 2.0908x; 1.0912x over previous
#include <cuda_runtime.h>
#include <cstddef>

// Shapes (fixed by the problem)
//  x_f:    (128, 256, 31, 31) f32
//  z_f:    (128, 256, 7, 7)   f32
//  heat_w: (1, 256, 3, 3), heat_b: (1,)
//  reg_w:  (4, 256, 3, 3), reg_b:  (4,)
//  out = concat(pred_heat (128,1,23,23), pred_reg (128,4,23,23)) f32

#define NB 128
#define NC 256
#define HEAT_ELEMS (NB * 529)          // 67712
#define OUT_ELEMS  (NB * 5 * 529)      // 338560

// smem layout (floats)
#define SX_SZ   (8 * 31 * 33)          // 8184  x tile, row stride 33
#define SZ_SZ   (8 * 49)               // 392   z taps
#define SC_SZ   (8 * 25 * 28)          // 5600  corr, row stride 28 (8B-aligned win)
#define SW_SZ   (8 * 5 * 12)           // 480   weights [ch][o][12], 9 used + pad
#define SMEM_FLOATS (SX_SZ + SZ_SZ + SC_SZ + SW_SZ)

// ---------------------------------------------------------------------------
// K0: write biases into out (out is poisoned to 0xAA by the harness).
// ---------------------------------------------------------------------------
__global__ void init_out_kernel(const float* __restrict__ heat_b,
                                const float* __restrict__ reg_b,
                                float* __restrict__ out)
{
    int i = blockIdx.x * 256 + threadIdx.x;
    if (i >= OUT_ELEMS) return;
    if (i < HEAT_ELEMS) {
        out[i] = heat_b[0];
    } else {
        int j = i - HEAT_ELEMS;
        int o = (j / 529) & 3;
        out[i] = reg_b[o];
    }
}

// ---------------------------------------------------------------------------
// K1 (fused): depthwise xcorr + both 3x3 head convs.
// Grid: 128*32 CTAs; CTA = (n, block of 8 channels). 256 threads.
// Phase B: 5x5 register corr tile / thread (FMA-bound, unchanged).
// Phase C: 2-pixel units; weights via LDS.128, window via LDS.64.
// ---------------------------------------------------------------------------
__global__ __launch_bounds__(256, 3)
void fused_kernel(const float* __restrict__ x_f, const float* __restrict__ z_f,
                  const float* __restrict__ heat_w, const float* __restrict__ reg_w,
                  float* __restrict__ out)
{
    extern __shared__ float sm[];
    float* sx = sm;
    float* sz = sx + SX_SZ;
    float* sc = sz + SZ_SZ;
    float* sw = sc + SC_SZ;

    const int b   = blockIdx.x;
    const int n   = b >> 5;
    const int c0  = (b & 31) * 8;
    const int tid = threadIdx.x;

    // --- Phase A: staging ---
    const float* xg = x_f + ((size_t)n * NC + c0) * 961;
    for (int i = tid; i < 8 * 961; i += 256) {
        int ch = i / 961;
        int p  = i - ch * 961;
        int r  = p / 31;
        int cc = p - r * 31;
        sx[ch * (31 * 33) + r * 33 + cc] = xg[i];
    }
    const float* zg = z_f + ((size_t)n * NC + c0) * 49;
    for (int i = tid; i < 8 * 49; i += 256) sz[i] = zg[i];

    // Weights: sw[ch*60 + o*12 + tap], tap 0..8 real, 9..11 zero pad.
    for (int i = tid; i < SW_SZ; i += 256) {
        int ch = i / 60, r = i - ch * 60;
        int o = r / 12, tap = r - o * 12;
        float v = 0.0f;
        if (tap < 9)
            v = (o == 0) ? heat_w[(c0 + ch) * 9 + tap]
                         : reg_w[(((o - 1) * NC) + c0 + ch) * 9 + tap];
        sw[i] = v;
    }
    // Zero corr pad columns 25..27 (read by the discarded 2nd pixel at x0=22).
    for (int i = tid; i < 8 * 25 * 3; i += 256) {
        int ch = i / 75, r2 = i - ch * 75;
        int r = r2 / 3, cp = 25 + (r2 - r * 3);
        sc[ch * 700 + r * 28 + cp] = 0.0f;
    }
    __syncthreads();

    // --- Phase B: depthwise xcorr, 5x5 register tile per thread ---
    if (tid < 200) {
        const int ch = tid / 25;
        const int t  = tid - ch * 25;
        const int ty = t / 5, tx = t - (t / 5) * 5;
        const int row0 = ty * 5, col0 = tx * 5;

        float zr[49];
        #pragma unroll
        for (int i = 0; i < 49; i++) zr[i] = sz[ch * 49 + i];

        float acc[25];
        #pragma unroll
        for (int i = 0; i < 25; i++) acc[i] = 0.0f;

        const float* sxc = sx + ch * (31 * 33) + row0 * 33 + col0;

        #pragma unroll
        for (int r = 0; r < 11; r++) {
            float xr[11];
            #pragma unroll
            for (int k = 0; k < 11; k++) xr[k] = sxc[r * 33 + k];
            #pragma unroll
            for (int dy = 0; dy < 5; dy++) {
                if (dy < r - 6 || dy > r) continue;   // static after unroll
                const int u = r - dy;
                #pragma unroll
                for (int v = 0; v < 7; v++) {
                    const float zv = zr[u * 7 + v];
                    #pragma unroll
                    for (int j = 0; j < 5; j++)
                        acc[dy * 5 + j] += zv * xr[v + j];
                }
            }
        }

        #pragma unroll
        for (int dy = 0; dy < 5; dy++)
            #pragma unroll
            for (int j = 0; j < 5; j++)
                sc[ch * 700 + (row0 + dy) * 28 + col0 + j] = acc[dy * 5 + j];
    }
    __syncthreads();

    // --- Phase C: partial 3x3 convs, 2-pixel units, vectorized smem loads ---
    // 276 units = 23 rows x 12 column-pairs; unit owns pixels (y,x0),(y,x0+1).
    for (int unit = tid; unit < 276; unit += 256) {
        const int y  = unit / 12;
        const int x0 = (unit - y * 12) * 2;

        float a0[5], a1[5];
        #pragma unroll
        for (int o = 0; o < 5; o++) { a0[o] = 0.0f; a1[o] = 0.0f; }

        #pragma unroll 2
        for (int ch = 0; ch < 8; ch++) {
            // 3x4 window shared by both pixels: 6 x LDS.64 (all 8B-aligned).
            const float* cb = sc + ch * 700 + y * 28 + x0;
            float win[3][4];
            #pragma unroll
            for (int dy = 0; dy < 3; dy++) {
                float2 p0 = *reinterpret_cast<const float2*>(cb + dy * 28);
                float2 p1 = *reinterpret_cast<const float2*>(cb + dy * 28 + 2);
                win[dy][0] = p0.x; win[dy][1] = p0.y;
                win[dy][2] = p1.x; win[dy][3] = p1.y;
            }
            #pragma unroll
            for (int o = 0; o < 5; o++) {
                // 9 weights via 3 x LDS.128 (warp-uniform broadcast).
                const float4* wp =
                    reinterpret_cast<const float4*>(sw + ch * 60 + o * 12);
                float4 wa = wp[0], wb = wp[1], wc = wp[2];
                float w[9] = {wa.x, wa.y, wa.z, wa.w,
                              wb.x, wb.y, wb.z, wb.w, wc.x};
                #pragma unroll
                for (int dy = 0; dy < 3; dy++)
                    #pragma unroll
                    for (int dx = 0; dx < 3; dx++) {
                        const float wv = w[dy * 3 + dx];
                        a0[o] += wv * win[dy][dx];
                        a1[o] += wv * win[dy][dx + 1];
                    }
            }
        }

        const int sp = y * 23 + x0;
        atomicAdd(&out[(size_t)n * 529 + sp], a0[0]);
        #pragma unroll
        for (int o = 0; o < 4; o++)
            atomicAdd(&out[HEAT_ELEMS + ((size_t)n * 4 + o) * 529 + sp], a0[1 + o]);
        if (x0 < 22) {                         // 2nd pixel valid unless x0==22
            atomicAdd(&out[(size_t)n * 529 + sp + 1], a1[0]);
            #pragma unroll
            for (int o = 0; o < 4; o++)
                atomicAdd(&out[HEAT_ELEMS + ((size_t)n * 4 + o) * 529 + sp + 1],
                          a1[1 + o]);
        }
    }
}

// ---------------------------------------------------------------------------
extern "C" void kernel_launch(void* const* d_in, const int* in_sizes, int n_in,
                              void* d_out, int out_size)
{
    const float *x_f = nullptr, *z_f = nullptr, *heat_w = nullptr,
                *heat_b = nullptr, *reg_w = nullptr, *reg_b = nullptr;
    for (int i = 0; i < n_in; i++) {
        switch (in_sizes[i]) {
            case 128 * 256 * 31 * 31: x_f    = (const float*)d_in[i]; break;
            case 128 * 256 * 7 * 7:   z_f    = (const float*)d_in[i]; break;
            case 1 * 256 * 3 * 3:     heat_w = (const float*)d_in[i]; break;
            case 1:                   heat_b = (const float*)d_in[i]; break;
            case 4 * 256 * 3 * 3:     reg_w  = (const float*)d_in[i]; break;
            case 4:                   reg_b  = (const float*)d_in[i]; break;
            default: break;
        }
    }
    float* out = (float*)d_out;

    const int smem1 = SMEM_FLOATS * (int)sizeof(float);   // ~58.6 KB
    cudaFuncSetAttribute(fused_kernel,
                         cudaFuncAttributeMaxDynamicSharedMemorySize, smem1);

    init_out_kernel<<<(OUT_ELEMS + 255) / 256, 256>>>(heat_b, reg_b, out);
    fused_kernel<<<NB * 32, 256, smem1>>>(x_f, z_f, heat_w, reg_w, out);
}

// round 5
// speedup vs baseline: 2.1189x; 1.0134x over previous
#include <cuda_runtime.h>
#include <cstddef>

// Shapes (fixed by the problem)
//  x_f:    (128, 256, 31, 31) f32
//  z_f:    (128, 256, 7, 7)   f32
//  heat_w: (1, 256, 3, 3), heat_b: (1,)
//  reg_w:  (4, 256, 3, 3), reg_b:  (4,)
//  out = concat(pred_heat (128,1,23,23), pred_reg (128,4,23,23)) f32

#define NB 128
#define NC 256
#define HEAT_ELEMS (NB * 529)          // 67712
#define OUT_ELEMS  (NB * 5 * 529)      // 338560

// smem layout (floats)
// x: per-channel stride 1049 = 31*33 + 26 pad  ==> 1049 mod 32 == 25, which
// makes Phase-B lane banks == (25*ch + y + const) mod 32 == (tid+const) mod 32:
// consecutive lanes -> consecutive banks, conflict-free.
#define X_CH_STRIDE 1049
#define SX_SZ   (8 * X_CH_STRIDE)      // 8392
#define SZ_SZ   (8 * 49)               // 392
#define SC_SZ   (8 * 25 * 28)          // 5600  corr, row stride 28 (8B-aligned)
#define SW_SZ   (8 * 5 * 12)           // 480   weights [ch][o][12]
#define SMEM_FLOATS (SX_SZ + SZ_SZ + SC_SZ + SW_SZ)

// ---------------------------------------------------------------------------
// K0: write biases into out (out is poisoned to 0xAA by the harness).
// ---------------------------------------------------------------------------
__global__ void init_out_kernel(const float* __restrict__ heat_b,
                                const float* __restrict__ reg_b,
                                float* __restrict__ out)
{
    int i = blockIdx.x * 256 + threadIdx.x;
    if (i >= OUT_ELEMS) return;
    if (i < HEAT_ELEMS) {
        out[i] = heat_b[0];
    } else {
        int j = i - HEAT_ELEMS;
        int o = (j / 529) & 3;
        out[i] = reg_b[o];
    }
}

// ---------------------------------------------------------------------------
// K1 (fused): depthwise xcorr + both 3x3 head convs.
// Grid: 128*32 CTAs; CTA = (n, block of 8 channels). 256 threads.
// Phase B: 1x25 corr-row tile per thread, conflict-free smem banks.
// Phase C: 2-pixel units; weights via LDS.128 broadcast, window via LDS.64.
// ---------------------------------------------------------------------------
__global__ __launch_bounds__(256, 3)
void fused_kernel(const float* __restrict__ x_f, const float* __restrict__ z_f,
                  const float* __restrict__ heat_w, const float* __restrict__ reg_w,
                  float* __restrict__ out)
{
    extern __shared__ float sm[];
    float* sx = sm;
    float* sz = sx + SX_SZ;
    float* sc = sz + SZ_SZ;
    float* sw = sc + SC_SZ;

    const int b   = blockIdx.x;
    const int n   = b >> 5;
    const int c0  = (b & 31) * 8;
    const int tid = threadIdx.x;

    // --- Phase A: staging ---
    const float* xg = x_f + ((size_t)n * NC + c0) * 961;
    for (int i = tid; i < 8 * 961; i += 256) {
        int ch = i / 961;
        int p  = i - ch * 961;
        int r  = p / 31;
        int cc = p - r * 31;
        sx[ch * X_CH_STRIDE + r * 33 + cc] = xg[i];
    }
    const float* zg = z_f + ((size_t)n * NC + c0) * 49;
    for (int i = tid; i < 8 * 49; i += 256) sz[i] = zg[i];

    // Weights: sw[ch*60 + o*12 + tap], tap 0..8 real, 9..11 zero pad.
    for (int i = tid; i < SW_SZ; i += 256) {
        int ch = i / 60, r = i - ch * 60;
        int o = r / 12, tap = r - o * 12;
        float v = 0.0f;
        if (tap < 9)
            v = (o == 0) ? heat_w[(c0 + ch) * 9 + tap]
                         : reg_w[(((o - 1) * NC) + c0 + ch) * 9 + tap];
        sw[i] = v;
    }
    // Zero corr pad columns 25..27 (read by the discarded 2nd pixel at x0=22).
    for (int i = tid; i < 8 * 25 * 3; i += 256) {
        int ch = i / 75, r2 = i - ch * 75;
        int r = r2 / 3, cp = 25 + (r2 - r * 3);
        sc[ch * 700 + r * 28 + cp] = 0.0f;
    }
    __syncthreads();

    // --- Phase B: depthwise xcorr, one 25-wide corr row per thread ---
    if (tid < 200) {
        const int ch = tid / 25;       // tid = 25*ch + y  -> conflict-free banks
        const int y  = tid - ch * 25;

        float acc[25];
        #pragma unroll
        for (int i = 0; i < 25; i++) acc[i] = 0.0f;

        const float* sxc = sx + ch * X_CH_STRIDE + y * 33;
        const float* szc = sz + ch * 49;

        #pragma unroll
        for (int u = 0; u < 7; u++) {
            float zrow[7];
            #pragma unroll
            for (int v = 0; v < 7; v++) zrow[v] = szc[u * 7 + v];

            float xr[31];
            #pragma unroll
            for (int k = 0; k < 31; k++) xr[k] = sxc[u * 33 + k];

            #pragma unroll
            for (int v = 0; v < 7; v++) {
                const float zv = zrow[v];
                #pragma unroll
                for (int j = 0; j < 25; j++)
                    acc[j] += zv * xr[v + j];
            }
        }

        // Store the corr row: 12 x STS.64 + 1 x STS.32 (8B-aligned).
        float* scr = sc + ch * 700 + y * 28;
        #pragma unroll
        for (int j = 0; j < 24; j += 2) {
            float2 p; p.x = acc[j]; p.y = acc[j + 1];
            *reinterpret_cast<float2*>(scr + j) = p;
        }
        scr[24] = acc[24];
    }
    __syncthreads();

    // --- Phase C: partial 3x3 convs, 2-pixel units, vectorized smem loads ---
    // 276 units = 23 rows x 12 column-pairs; unit owns pixels (y,x0),(y,x0+1).
    float* outh = out + (size_t)n * 529;
    float* outr = out + HEAT_ELEMS + (size_t)n * 4 * 529;

    for (int unit = tid; unit < 276; unit += 256) {
        const int y  = unit / 12;
        const int x0 = (unit - y * 12) * 2;

        float a0[5], a1[5];
        #pragma unroll
        for (int o = 0; o < 5; o++) { a0[o] = 0.0f; a1[o] = 0.0f; }

        #pragma unroll 2
        for (int ch = 0; ch < 8; ch++) {
            // 3x4 window shared by both pixels: 6 x LDS.64 (all 8B-aligned).
            const float* cb = sc + ch * 700 + y * 28 + x0;
            float win[3][4];
            #pragma unroll
            for (int dy = 0; dy < 3; dy++) {
                float2 p0 = *reinterpret_cast<const float2*>(cb + dy * 28);
                float2 p1 = *reinterpret_cast<const float2*>(cb + dy * 28 + 2);
                win[dy][0] = p0.x; win[dy][1] = p0.y;
                win[dy][2] = p1.x; win[dy][3] = p1.y;
            }
            #pragma unroll
            for (int o = 0; o < 5; o++) {
                // 9 weights via 3 x LDS.128 (warp-uniform broadcast).
                const float4* wp =
                    reinterpret_cast<const float4*>(sw + ch * 60 + o * 12);
                float4 wa = wp[0], wb = wp[1], wc = wp[2];
                float w[9] = {wa.x, wa.y, wa.z, wa.w,
                              wb.x, wb.y, wb.z, wb.w, wc.x};
                #pragma unroll
                for (int dy = 0; dy < 3; dy++)
                    #pragma unroll
                    for (int dx = 0; dx < 3; dx++) {
                        const float wv = w[dy * 3 + dx];
                        a0[o] += wv * win[dy][dx];
                        a1[o] += wv * win[dy][dx + 1];
                    }
            }
        }

        const int sp = y * 23 + x0;
        atomicAdd(&outh[sp], a0[0]);
        #pragma unroll
        for (int o = 0; o < 4; o++)
            atomicAdd(&outr[o * 529 + sp], a0[1 + o]);
        if (x0 < 22) {                         // 2nd pixel valid unless x0==22
            atomicAdd(&outh[sp + 1], a1[0]);
            #pragma unroll
            for (int o = 0; o < 4; o++)
                atomicAdd(&outr[o * 529 + sp + 1], a1[1 + o]);
        }
    }
}

// ---------------------------------------------------------------------------
extern "C" void kernel_launch(void* const* d_in, const int* in_sizes, int n_in,
                              void* d_out, int out_size)
{
    const float *x_f = nullptr, *z_f = nullptr, *heat_w = nullptr,
                *heat_b = nullptr, *reg_w = nullptr, *reg_b = nullptr;
    for (int i = 0; i < n_in; i++) {
        switch (in_sizes[i]) {
            case 128 * 256 * 31 * 31: x_f    = (const float*)d_in[i]; break;
            case 128 * 256 * 7 * 7:   z_f    = (const float*)d_in[i]; break;
            case 1 * 256 * 3 * 3:     heat_w = (const float*)d_in[i]; break;
            case 1:                   heat_b = (const float*)d_in[i]; break;
            case 4 * 256 * 3 * 3:     reg_w  = (const float*)d_in[i]; break;
            case 4:                   reg_b  = (const float*)d_in[i]; break;
            default: break;
        }
    }
    float* out = (float*)d_out;

    const int smem1 = SMEM_FLOATS * (int)sizeof(float);   // ~59.5 KB
    cudaFuncSetAttribute(fused_kernel,
                         cudaFuncAttributeMaxDynamicSharedMemorySize, smem1);

    init_out_kernel<<<(OUT_ELEMS + 255) / 256, 256>>>(heat_b, reg_b, out);
    fused_kernel<<<NB * 32, 256, smem1>>>(x_f, z_f, heat_w, reg_w, out);
}

// round 6
// speedup vs baseline: 2.2768x; 1.0745x over previous
#include <cuda_runtime.h>
#include <cstddef>

// Shapes (fixed by the problem)
//  x_f:    (128, 256, 31, 31) f32
//  z_f:    (128, 256, 7, 7)   f32
//  heat_w: (1, 256, 3, 3), heat_b: (1,)
//  reg_w:  (4, 256, 3, 3), reg_b:  (4,)
//  out = concat(pred_heat (128,1,23,23), pred_reg (128,4,23,23)) f32

#define NB 128
#define NC 256
#define HEAT_ELEMS (NB * 529)          // 67712
#define OUT_ELEMS  (NB * 5 * 529)      // 338560

typedef unsigned long long ull;

// Packed f32x2 FMA (two independent exact fp32 FMAs in one instruction).
__device__ __forceinline__ ull fma2(ull a, ull b, ull c) {
    ull d;
    asm("fma.rn.f32x2 %0, %1, %2, %3;" : "=l"(d) : "l"(a), "l"(b), "l"(c));
    return d;
}

// smem layout, all in channel-PAIR-packed float2 (stored as floats):
//  sx2: 4 pairs x 31 rows x 34 f2  (row stride 34 f2 == 2 mod 16 -> the
//       y=rem/2, half=rem&1 Phase-B mapping gives disjoint even/odd bank
//       residues => conflict-free LDS.64)
//  sz2: 4 x 49 f2
//  sc2: 4 x 25 x 26 f2 (corr; stride even => 16B-aligned window LDS.128)
//  sw2: 4 pairs x 5 o x 9 taps f2
#define SX_F   (4 * 31 * 34 * 2)       // 8432 floats
#define SZ_F   (4 * 49 * 2)            // 392
#define SC_F   (4 * 25 * 26 * 2)       // 5200
#define SW_F   (4 * 5 * 9 * 2)         // 360
#define SMEM_FLOATS (SX_F + SZ_F + SC_F + SW_F)   // 14384 -> 57536 B

// ---------------------------------------------------------------------------
// K0: write biases into out (out is poisoned to 0xAA by the harness).
// ---------------------------------------------------------------------------
__global__ void init_out_kernel(const float* __restrict__ heat_b,
                                const float* __restrict__ reg_b,
                                float* __restrict__ out)
{
    int i = blockIdx.x * 256 + threadIdx.x;
    if (i >= OUT_ELEMS) return;
    if (i < HEAT_ELEMS) {
        out[i] = heat_b[0];
    } else {
        int j = i - HEAT_ELEMS;
        int o = (j / 529) & 3;
        out[i] = reg_b[o];
    }
}

// ---------------------------------------------------------------------------
// K1 (fused): depthwise xcorr + both 3x3 head convs, channel-pair f32x2.
// Grid: 128*32 CTAs; CTA = (n, block of 8 channels). 256 threads.
// ---------------------------------------------------------------------------
__global__ __launch_bounds__(256, 3)
void fused_kernel(const float* __restrict__ x_f, const float* __restrict__ z_f,
                  const float* __restrict__ heat_w, const float* __restrict__ reg_w,
                  float* __restrict__ out)
{
    extern __shared__ __align__(16) float sm[];
    float* sxf = sm;                 // pair-interleaved x
    float* szf = sxf + SX_F;         // pair-interleaved z
    float* scf = szf + SZ_F;         // pair-interleaved corr
    float* swf = scf + SC_F;         // pair-interleaved weights

    ull* sx2 = reinterpret_cast<ull*>(sxf);
    ull* sz2 = reinterpret_cast<ull*>(szf);
    ull* sc2 = reinterpret_cast<ull*>(scf);
    ull* sw2 = reinterpret_cast<ull*>(swf);

    const int b   = blockIdx.x;
    const int n   = b >> 5;
    const int c0  = (b & 31) * 8;
    const int tid = threadIdx.x;

    // --- Phase A: staging into pair-interleaved layouts ---
    const float* xg = x_f + ((size_t)n * NC + c0) * 961;
    for (int i = tid; i < 8 * 961; i += 256) {
        int ch = i / 961;
        int q  = i - ch * 961;
        int r  = q / 31;
        int c  = q - r * 31;
        sxf[(((ch >> 1) * (31 * 34)) + r * 34 + c) * 2 + (ch & 1)] = xg[i];
    }
    const float* zg = z_f + ((size_t)n * NC + c0) * 49;
    for (int i = tid; i < 8 * 49; i += 256) {
        int ch = i / 49;
        int t  = i - ch * 49;
        szf[((ch >> 1) * 49 + t) * 2 + (ch & 1)] = zg[i];
    }
    for (int i = tid; i < 360; i += 256) {          // (ch, o, tap)
        int ch  = i / 45;
        int rr  = i - ch * 45;
        int o   = rr / 9;
        int tap = rr - o * 9;
        float v = (o == 0) ? heat_w[(c0 + ch) * 9 + tap]
                           : reg_w[(((o - 1) * NC) + c0 + ch) * 9 + tap];
        swf[((((ch >> 1) * 5) + o) * 9 + tap) * 2 + (ch & 1)] = v;
    }
    __syncthreads();

    // --- Phase B: depthwise xcorr, 13-col half-row of a channel PAIR ---
    if (tid < 200) {
        const int p    = tid / 50;           // channel pair 0..3
        const int rem  = tid - p * 50;
        const int y    = rem >> 1;           // corr row 0..24
        const int half = rem & 1;
        const int x0   = half ? 13 : 0;      // cols x0..x0+12 (13th dropped h1)

        ull acc[13];
        #pragma unroll
        for (int j = 0; j < 13; j++) acc[j] = 0ull;

        const ull* xb = sx2 + p * (31 * 34) + x0;
        const ull* zb = sz2 + p * 49;

        #pragma unroll
        for (int u = 0; u < 7; u++) {
            const ull* xrow = xb + (y + u) * 34;
            ull xr[19];
            #pragma unroll
            for (int k = 0; k < 19; k++) xr[k] = xrow[k];
            #pragma unroll
            for (int v = 0; v < 7; v++) {
                const ull zv = zb[u * 7 + v];
                #pragma unroll
                for (int j = 0; j < 13; j++)
                    acc[j] = fma2(zv, xr[v + j], acc[j]);
            }
        }

        ull* crow = sc2 + p * 650 + y * 26 + x0;
        #pragma unroll
        for (int j = 0; j < 13; j++)
            if (x0 + j <= 24) crow[j] = acc[j];   // half1 drops j==12
    }
    __syncthreads();

    // --- Phase C: partial 3x3 convs, 2-pixel units, pair-packed FFMA2 ---
    float* outh = out + (size_t)n * 529;
    float* outr = out + HEAT_ELEMS + (size_t)n * 4 * 529;

    for (int unit = tid; unit < 276; unit += 256) {
        const int y  = unit / 12;
        const int x0 = (unit - y * 12) * 2;

        ull a0[5], a1[5];
        #pragma unroll
        for (int o = 0; o < 5; o++) { a0[o] = 0ull; a1[o] = 0ull; }

        #pragma unroll
        for (int p = 0; p < 4; p++) {
            const ull* cb = sc2 + p * 650 + y * 26 + x0;
            ull win[3][4];
            #pragma unroll
            for (int dy = 0; dy < 3; dy++) {
                ulonglong2 t0 = *reinterpret_cast<const ulonglong2*>(cb + dy * 26);
                ulonglong2 t1 = *reinterpret_cast<const ulonglong2*>(cb + dy * 26 + 2);
                win[dy][0] = t0.x; win[dy][1] = t0.y;
                win[dy][2] = t1.x; win[dy][3] = t1.y;
            }
            #pragma unroll
            for (int o = 0; o < 5; o++) {
                const ull* wp = sw2 + ((p * 5) + o) * 9;   // broadcast loads
                #pragma unroll
                for (int dy = 0; dy < 3; dy++)
                    #pragma unroll
                    for (int dx = 0; dx < 3; dx++) {
                        const ull w = wp[dy * 3 + dx];
                        a0[o] = fma2(w, win[dy][dx],     a0[o]);
                        a1[o] = fma2(w, win[dy][dx + 1], a1[o]);
                    }
            }
        }

        const int sp = y * 23 + x0;
        {
            float2 f = *reinterpret_cast<float2*>(&a0[0]);
            atomicAdd(&outh[sp], f.x + f.y);
        }
        #pragma unroll
        for (int o = 0; o < 4; o++) {
            float2 f = *reinterpret_cast<float2*>(&a0[1 + o]);
            atomicAdd(&outr[o * 529 + sp], f.x + f.y);
        }
        if (x0 < 22) {                        // 2nd pixel valid unless x0==22
            float2 fh = *reinterpret_cast<float2*>(&a1[0]);
            atomicAdd(&outh[sp + 1], fh.x + fh.y);
            #pragma unroll
            for (int o = 0; o < 4; o++) {
                float2 f = *reinterpret_cast<float2*>(&a1[1 + o]);
                atomicAdd(&outr[o * 529 + sp + 1], f.x + f.y);
            }
        }
    }
}

// ---------------------------------------------------------------------------
extern "C" void kernel_launch(void* const* d_in, const int* in_sizes, int n_in,
                              void* d_out, int out_size)
{
    const float *x_f = nullptr, *z_f = nullptr, *heat_w = nullptr,
                *heat_b = nullptr, *reg_w = nullptr, *reg_b = nullptr;
    for (int i = 0; i < n_in; i++) {
        switch (in_sizes[i]) {
            case 128 * 256 * 31 * 31: x_f    = (const float*)d_in[i]; break;
            case 128 * 256 * 7 * 7:   z_f    = (const float*)d_in[i]; break;
            case 1 * 256 * 3 * 3:     heat_w = (const float*)d_in[i]; break;
            case 1:                   heat_b = (const float*)d_in[i]; break;
            case 4 * 256 * 3 * 3:     reg_w  = (const float*)d_in[i]; break;
            case 4:                   reg_b  = (const float*)d_in[i]; break;
            default: break;
        }
    }
    float* out = (float*)d_out;

    const int smem1 = SMEM_FLOATS * (int)sizeof(float);   // 57536 B
    cudaFuncSetAttribute(fused_kernel,
                         cudaFuncAttributeMaxDynamicSharedMemorySize, smem1);

    init_out_kernel<<<(OUT_ELEMS + 255) / 256, 256>>>(heat_b, reg_b, out);
    fused_kernel<<<NB * 32, 256, smem1>>>(x_f, z_f, heat_w, reg_w, out);
}